// round 2
// baseline (speedup 1.0000x reference)
#include <cuda_runtime.h>
#include <math.h>

#define BATCH 2
#define NPTS 4096
#define MPTS 4096
#define NSTEPS 8
#define TOLER 1e-6f

#define TPB_A 128
#define MSPLIT 8
#define MCH (MPTS / MSPLIT)       // 512 targets per block tile
#define NCHUNK (NPTS / TPB_A)     // 32 source chunks

#define RB_TPB 256
#define RB_BLK (NPTS / RB_TPB)    // 16 blocks per batch
#define TOT_RB (BATCH * RB_BLK)   // 32 blocks total

// ---------------- device state ----------------
__device__ float4 g_tgt4[BATCH * MPTS];                 // (x,y,z,|t|^2)
__device__ unsigned long long g_scr[BATCH * NPTS];      // packed (key|idx) per source point
__device__ float g_part[BATCH][RB_BLK][16];             // per-block partial sums
__device__ float g_Rcum[BATCH][9];
__device__ float g_tcum[BATCH][3];
__device__ float g_err[BATCH];
__device__ int g_done;
__device__ int g_count;

// ---------------- init ----------------
__global__ void init_kernel(const float* __restrict__ ptgt) {
    int i = blockIdx.x * blockDim.x + threadIdx.x;  // 0..8191
    if (i < BATCH * MPTS) {
        float x = ptgt[i * 3 + 0];
        float y = ptgt[i * 3 + 1];
        float z = ptgt[i * 3 + 2];
        g_tgt4[i] = make_float4(x, y, z, x * x + y * y + z * z);
        g_scr[i] = 0xFFFFFFFFFFFFFFFFull;
    }
    if (i == 0) { g_done = 0; g_count = 0; }
    if (i < BATCH) {
        g_err[i] = 0.0f;
        float* R = g_Rcum[i];
        R[0] = 1.f; R[1] = 0.f; R[2] = 0.f;
        R[3] = 0.f; R[4] = 1.f; R[5] = 0.f;
        R[6] = 0.f; R[7] = 0.f; R[8] = 1.f;
        g_tcum[i][0] = 0.f; g_tcum[i][1] = 0.f; g_tcum[i][2] = 0.f;
    }
}

// ---------------- NN search (split targets, atomicMin combine) ----------------
__global__ __launch_bounds__(TPB_A) void nn_kernel(const float* __restrict__ psrc) {
    __shared__ float4 sh[MCH];
    const int b = blockIdx.z;
    const int n = blockIdx.x * TPB_A + threadIdx.x;
    const int mbase = blockIdx.y * MCH;

    const float* Rc = g_Rcum[b];
    const float R0 = Rc[0], R1 = Rc[1], R2 = Rc[2];
    const float R3 = Rc[3], R4 = Rc[4], R5 = Rc[5];
    const float R6 = Rc[6], R7 = Rc[7], R8 = Rc[8];
    const float t0 = g_tcum[b][0], t1 = g_tcum[b][1], t2 = g_tcum[b][2];

    const float* ps = psrc + ((size_t)b * NPTS + n) * 3;
    const float x = ps[0], y = ps[1], z = ps[2];
    const float px = R0 * x + R1 * y + R2 * z + t0;
    const float py = R3 * x + R4 * y + R5 * z + t1;
    const float pz = R6 * x + R7 * y + R8 * z + t2;
    const float ax = -2.0f * px, ay = -2.0f * py, az = -2.0f * pz;

    for (int i = threadIdx.x; i < MCH; i += TPB_A)
        sh[i] = g_tgt4[b * MPTS + mbase + i];
    __syncthreads();

    float bs = 3.0e38f;
    int bi = 0;
#pragma unroll 8
    for (int m = 0; m < MCH; m++) {
        float4 t = sh[m];
        float s = __fmaf_rn(ax, t.x, t.w);
        s = __fmaf_rn(ay, t.y, s);
        s = __fmaf_rn(az, t.z, s);
        if (s < bs) { bs = s; bi = m; }
    }

    // orderable mapping for signed float bits (s can be slightly negative)
    unsigned u = __float_as_uint(bs);
    u = (u & 0x80000000u) ? ~u : (u | 0x80000000u);
    unsigned long long key =
        ((unsigned long long)u << 32) | (unsigned)(mbase + bi);
    atomicMin(g_scr + (size_t)b * NPTS + n, key);
}

// ---------------- Horn quaternion Kabsch (single thread, per batch) ----------------
__device__ __forceinline__ void matmul4(float* C, const float* A, const float* Bm) {
#pragma unroll
    for (int i = 0; i < 4; i++)
#pragma unroll
        for (int j = 0; j < 4; j++) {
            float a = 0.f;
#pragma unroll
            for (int k = 0; k < 4; k++) a = __fmaf_rn(A[i * 4 + k], Bm[k * 4 + j], a);
            C[i * 4 + j] = a;
        }
}

__device__ void solve_horn(const double* S, double* Rn, double* tn) {
    const double n = (double)NPTS;
    const double inv = 1.0 / n;
    const double pmx = S[0] * inv, pmy = S[1] * inv, pmz = S[2] * inv;
    const double qmx = S[3] * inv, qmy = S[4] * inv, qmz = S[5] * inv;

    const double Sxx = S[6]  - n * pmx * qmx, Sxy = S[7]  - n * pmx * qmy, Sxz = S[8]  - n * pmx * qmz;
    const double Syx = S[9]  - n * pmy * qmx, Syy = S[10] - n * pmy * qmy, Syz = S[11] - n * pmy * qmz;
    const double Szx = S[12] - n * pmz * qmx, Szy = S[13] - n * pmz * qmy, Szz = S[14] - n * pmz * qmz;

    double K[16];
    K[0]  = Sxx + Syy + Szz; K[1]  = Syz - Szy;       K[2]  = Szx - Sxz;       K[3]  = Sxy - Syx;
    K[5]  = Sxx - Syy - Szz; K[6]  = Sxy + Syx;       K[7]  = Szx + Sxz;
    K[10] = -Sxx + Syy - Szz; K[11] = Syz + Szy;
    K[15] = -Sxx - Syy + Szz;
    K[4] = K[1]; K[8] = K[2]; K[12] = K[3]; K[9] = K[6]; K[13] = K[7]; K[14] = K[11];

    double fro = 0.0;
#pragma unroll
    for (int i = 0; i < 16; i++) fro += K[i] * K[i];
    const double sc = 1.0 / sqrt(fro + 1e-300);

    float Kf[16];
#pragma unroll
    for (int i = 0; i < 16; i++) Kf[i] = (float)(K[i] * sc);
    Kf[0] += 1.f; Kf[5] += 1.f; Kf[10] += 1.f; Kf[15] += 1.f;  // eigs in [0,2]

    float K2[16], K4[16];
    matmul4(K2, Kf, Kf);
    matmul4(K4, K2, K2);   // ratio^4 convergence per iteration

    float v0 = 1.f, v1 = 0.02f, v2 = 0.03f, v3 = 0.04f;
#pragma unroll 4
    for (int it = 0; it < 48; it++) {
        float w0 = K4[0]  * v0 + K4[1]  * v1 + K4[2]  * v2 + K4[3]  * v3;
        float w1 = K4[4]  * v0 + K4[5]  * v1 + K4[6]  * v2 + K4[7]  * v3;
        float w2 = K4[8]  * v0 + K4[9]  * v1 + K4[10] * v2 + K4[11] * v3;
        float w3 = K4[12] * v0 + K4[13] * v1 + K4[14] * v2 + K4[15] * v3;
        if ((it & 3) == 3) {
            float r = rsqrtf(w0 * w0 + w1 * w1 + w2 * w2 + w3 * w3 + 1e-30f);
            w0 *= r; w1 *= r; w2 *= r; w3 *= r;
        }
        v0 = w0; v1 = w1; v2 = w2; v3 = w3;
    }

    const double qw = v0, qx = v1, qy = v2, qz = v3;
    const double nn = qw * qw + qx * qx + qy * qy + qz * qz;
    const double s2 = 2.0 / nn;
    Rn[0] = 1.0 - s2 * (qy * qy + qz * qz); Rn[1] = s2 * (qx * qy - qw * qz); Rn[2] = s2 * (qx * qz + qw * qy);
    Rn[3] = s2 * (qx * qy + qw * qz); Rn[4] = 1.0 - s2 * (qx * qx + qz * qz); Rn[5] = s2 * (qy * qz - qw * qx);
    Rn[6] = s2 * (qx * qz - qw * qy); Rn[7] = s2 * (qy * qz + qw * qx); Rn[8] = 1.0 - s2 * (qx * qx + qy * qy);

    tn[0] = qmx - (Rn[0] * pmx + Rn[1] * pmy + Rn[2] * pmz);
    tn[1] = qmy - (Rn[3] * pmx + Rn[4] * pmy + Rn[5] * pmz);
    tn[2] = qmz - (Rn[6] * pmx + Rn[7] * pmy + Rn[8] * pmz);
}

// ---------------- reduce + Kabsch + compose + re-arm ----------------
__global__ __launch_bounds__(RB_TPB) void reduce_kernel(const float* __restrict__ psrc) {
    const int b = blockIdx.y;
    const int n = blockIdx.x * RB_TPB + threadIdx.x;

    const float* Rc = g_Rcum[b];
    const float R0 = Rc[0], R1 = Rc[1], R2 = Rc[2];
    const float R3 = Rc[3], R4 = Rc[4], R5 = Rc[5];
    const float R6 = Rc[6], R7 = Rc[7], R8 = Rc[8];
    const float t0 = g_tcum[b][0], t1 = g_tcum[b][1], t2 = g_tcum[b][2];

    const float* ps = psrc + ((size_t)b * NPTS + n) * 3;
    const float x = ps[0], y = ps[1], z = ps[2];
    const float px = R0 * x + R1 * y + R2 * z + t0;
    const float py = R3 * x + R4 * y + R5 * z + t1;
    const float pz = R6 * x + R7 * y + R8 * z + t2;

    const unsigned long long key = g_scr[(size_t)b * NPTS + n];
    unsigned u = (unsigned)(key >> 32);
    unsigned fb = (u & 0x80000000u) ? (u ^ 0x80000000u) : ~u;
    const float s = __uint_as_float(fb);
    const int idx = (int)(unsigned)(key & 0xFFFFFFFFull);

    const float pn = px * px + py * py + pz * pz;
    const float dist = sqrtf(fmaxf(pn + s, 0.0f));
    const float4 q = g_tgt4[b * MPTS + idx];

    float v[16];
    v[0] = px; v[1] = py; v[2] = pz;
    v[3] = q.x; v[4] = q.y; v[5] = q.z;
    v[6] = px * q.x; v[7] = px * q.y; v[8] = px * q.z;
    v[9] = py * q.x; v[10] = py * q.y; v[11] = py * q.z;
    v[12] = pz * q.x; v[13] = pz * q.y; v[14] = pz * q.z;
    v[15] = dist;

#pragma unroll
    for (int k = 0; k < 16; k++) {
        float a = v[k];
        a += __shfl_down_sync(0xffffffffu, a, 16);
        a += __shfl_down_sync(0xffffffffu, a, 8);
        a += __shfl_down_sync(0xffffffffu, a, 4);
        a += __shfl_down_sync(0xffffffffu, a, 2);
        a += __shfl_down_sync(0xffffffffu, a, 1);
        v[k] = a;
    }

    __shared__ float sm[RB_TPB / 32][16];
    const int lane = threadIdx.x & 31;
    const int warp = threadIdx.x >> 5;
    if (lane == 0) {
#pragma unroll
        for (int k = 0; k < 16; k++) sm[warp][k] = v[k];
    }
    __syncthreads();
    if (threadIdx.x < 16) {
        float a = 0.f;
#pragma unroll
        for (int w = 0; w < RB_TPB / 32; w++) a += sm[w][threadIdx.x];  // fixed order: deterministic
        g_part[b][blockIdx.x][threadIdx.x] = a;
        __threadfence();
    }
    __syncthreads();

    __shared__ int s_last;
    if (threadIdx.x == 0) {
        int t = atomicAdd(&g_count, 1);
        s_last = (t == TOT_RB - 1) ? 1 : 0;
    }
    __syncthreads();
    if (!s_last) return;
    __threadfence();

    // ---- last block: control + Kabsch solve ----
    __shared__ float s_en[BATCH];
    __shared__ int s_done;
    double S[16];
    if (threadIdx.x < BATCH) {
        volatile const float* gp = &g_part[0][0][0];
#pragma unroll
        for (int k = 0; k < 16; k++) S[k] = 0.0;
        for (int blk = 0; blk < RB_BLK; blk++)
#pragma unroll
            for (int k = 0; k < 16; k++)
                S[k] += (double)gp[((size_t)threadIdx.x * RB_BLK + blk) * 16 + k];
        s_en[threadIdx.x] = (float)(S[15] / (double)NPTS);
    }
    __syncthreads();
    if (threadIdx.x == 0) {
        int conv = (fabsf(s_en[0] - g_err[0]) < TOLER) &&
                   (fabsf(s_en[1] - g_err[1]) < TOLER);
        s_done = (g_done || conv) ? 1 : 0;
        g_done = s_done;
        g_count = 0;
    }
    __syncthreads();

    if (threadIdx.x < BATCH && !s_done) {
        const int bb = threadIdx.x;
        double Rn[9], tn[3];
        solve_horn(S, Rn, tn);

        double Ro[9], to[3];
#pragma unroll
        for (int i = 0; i < 9; i++) Ro[i] = (double)g_Rcum[bb][i];
#pragma unroll
        for (int i = 0; i < 3; i++) to[i] = (double)g_tcum[bb][i];

        double Rm[9], tm[3];
#pragma unroll
        for (int i = 0; i < 3; i++) {
#pragma unroll
            for (int j = 0; j < 3; j++)
                Rm[i * 3 + j] = Rn[i * 3 + 0] * Ro[0 + j] +
                                Rn[i * 3 + 1] * Ro[3 + j] +
                                Rn[i * 3 + 2] * Ro[6 + j];
            tm[i] = Rn[i * 3 + 0] * to[0] + Rn[i * 3 + 1] * to[1] +
                    Rn[i * 3 + 2] * to[2] + tn[i];
        }
#pragma unroll
        for (int i = 0; i < 9; i++) g_Rcum[bb][i] = (float)Rm[i];
#pragma unroll
        for (int i = 0; i < 3; i++) g_tcum[bb][i] = (float)tm[i];
        g_err[bb] = s_en[bb];
    }

    // re-arm NN scratch for next step
    for (int i = threadIdx.x; i < BATCH * NPTS; i += RB_TPB)
        g_scr[i] = 0xFFFFFFFFFFFFFFFFull;
}

// ---------------- final: quaternionize composed transform ----------------
__global__ void final_kernel(float* __restrict__ out) {
    const int b = threadIdx.x;
    if (b >= BATCH) return;
    const float* R = g_Rcum[b];
    out[b * 7 + 0] = g_tcum[b][0];
    out[b * 7 + 1] = g_tcum[b][1];
    out[b * 7 + 2] = g_tcum[b][2];
    const float r00 = R[0], r11 = R[4], r22 = R[8];
    float qw = 0.5f * sqrtf(fmaxf(1.f + r00 + r11 + r22, 1e-12f));
    float qx = 0.5f * sqrtf(fmaxf(1.f + r00 - r11 - r22, 1e-12f));
    float qy = 0.5f * sqrtf(fmaxf(1.f - r00 + r11 - r22, 1e-12f));
    float qz = 0.5f * sqrtf(fmaxf(1.f - r00 - r11 + r22, 1e-12f));
    qx = (R[7] - R[5] >= 0.f) ? qx : -qx;  // R21 - R12
    qy = (R[2] - R[6] >= 0.f) ? qy : -qy;  // R02 - R20
    qz = (R[3] - R[1] >= 0.f) ? qz : -qz;  // R10 - R01
    out[b * 7 + 3] = qx;
    out[b * 7 + 4] = qy;
    out[b * 7 + 5] = qz;
    out[b * 7 + 6] = qw;
}

// ---------------- launch ----------------
extern "C" void kernel_launch(void* const* d_in, const int* in_sizes, int n_in,
                              void* d_out, int out_size) {
    const float* psrc = (const float*)d_in[0];
    const float* ptgt = (const float*)d_in[1];
    float* out = (float*)d_out;

    init_kernel<<<(BATCH * MPTS + 255) / 256, 256>>>(ptgt);

    for (int s = 0; s < NSTEPS; s++) {
        dim3 gA(NCHUNK, MSPLIT, BATCH);
        nn_kernel<<<gA, TPB_A>>>(psrc);
        dim3 gB(RB_BLK, BATCH);
        reduce_kernel<<<gB, RB_TPB>>>(psrc);
    }
    final_kernel<<<1, 32>>>(out);
}